// round 4
// baseline (speedup 1.0000x reference)
#include <cuda_runtime.h>
#include <cstdint>

#define NMAX 100000

// ---- scratch (no allocations allowed -> __device__ globals) ----
__device__ int    g_deg[NMAX];
__device__ float  g_dinv[NMAX];
__device__ float4 g_g1[NMAX * 16];    // [N,64] as float4
__device__ float4 g_agg1[NMAX * 16];
__device__ float4 g_g2[NMAX * 8];     // [N,32] as float4
__device__ float4 g_agg2[NMAX * 8];
__device__ int    g_idx64;

__device__ __forceinline__ void red_add_v4(float* addr, float4 v) {
    asm volatile("red.global.add.v4.f32 [%0], {%1,%2,%3,%4};"
                 :: "l"(addr), "f"(v.x), "f"(v.y), "f"(v.z), "f"(v.w)
                 : "memory");
}

// Detect whether edge_index is int64 or int32. Node ids < 2^31, so for int64
// every odd 32-bit word (high half) is 0. 64 random int32 ids all-zero: ~never.
__global__ void detect_kernel(const unsigned int* __restrict__ w) {
    if (threadIdx.x == 0 && blockIdx.x == 0) {
        int all0 = 1;
        for (int i = 1; i < 129; i += 2) all0 &= (w[i] == 0u);
        g_idx64 = all0;
    }
}

__global__ void deg_init_kernel(int n) {
    int i = blockIdx.x * blockDim.x + threadIdx.x;
    if (i < n) g_deg[i] = 1;  // self-loop
}

__global__ void deg_count_kernel(const void* __restrict__ ei, int e) {
    int i = blockIdx.x * blockDim.x + threadIdx.x;
    if (i >= e) return;
    int is64 = g_idx64;
    int d;
    if (is64) d = (int)((const long long*)ei)[(size_t)e + i];
    else      d = ((const int*)ei)[(size_t)e + i];
    atomicAdd(&g_deg[d], 1);
}

__global__ void dinv_kernel(int n) {
    int i = blockIdx.x * blockDim.x + threadIdx.x;
    if (i < n) g_dinv[i] = rsqrtf((float)g_deg[i]);
}

// g1[i] = dinv[i] * (x[i] @ W1);  agg1[i] = g1[i]  (self-loop seed)
// block: (16,16) = 256 thr, 16 nodes/block, thread = (feat-quad fx, node j)
__global__ void gemm1_kernel(const float* __restrict__ x,
                             const float* __restrict__ W1, int n) {
    __shared__ float4 Ws[128 * 16];   // W1 [128][64] as float4 (32KB)
    __shared__ float  xs[16 * 129];   // 16 rows of x, padded (8.25KB)
    int tid = threadIdx.y * 16 + threadIdx.x;
    const float4* W4 = (const float4*)W1;
    for (int i = tid; i < 128 * 16; i += 256) Ws[i] = W4[i];
    int base = blockIdx.x * 16;
    for (int i = tid; i < 16 * 128; i += 256) {
        int j = i >> 7, k = i & 127;
        int node = base + j;
        xs[j * 129 + k] = (node < n) ? x[(size_t)node * 128 + k] : 0.f;
    }
    __syncthreads();
    int fx = threadIdx.x, j = threadIdx.y;
    float4 acc = make_float4(0.f, 0.f, 0.f, 0.f);
    const float* xr = &xs[j * 129];
#pragma unroll
    for (int k = 0; k < 128; k++) {
        float xv = xr[k];
        float4 w = Ws[k * 16 + fx];
        acc.x += xv * w.x; acc.y += xv * w.y;
        acc.z += xv * w.z; acc.w += xv * w.w;
    }
    int node = base + j;
    if (node < n) {
        float dv = g_dinv[node];
        float4 gv = make_float4(acc.x * dv, acc.y * dv, acc.z * dv, acc.w * dv);
        g_g1[node * 16 + fx]   = gv;
        g_agg1[node * 16 + fx] = gv;
    }
}

// layer1 scatter: agg1[dst] += g1[src]   (16 threads/edge, float4 chunks)
__global__ void edge1_kernel(const void* __restrict__ ei, int e) {
    unsigned int t = blockIdx.x * blockDim.x + threadIdx.x;
    if (t >= (unsigned int)e * 16u) return;
    int eid = (int)(t >> 4), c = (int)(t & 15u);
    int is64 = g_idx64;
    int s, d;
    if (is64) {
        const long long* p = (const long long*)ei;
        s = (int)p[eid]; d = (int)p[(size_t)e + eid];
    } else {
        const int* p = (const int*)ei;
        s = p[eid]; d = p[(size_t)e + eid];
    }
    float4 v = g_g1[(size_t)s * 16 + c];
    red_add_v4((float*)g_agg1 + (size_t)d * 64 + c * 4, v);
}

// epilogue1 + GEMM2: hrelu = relu(dinv*agg1 + b1); g2 = dinv*(hrelu@W2); agg2=g2
// block: (8,32) = 256 thr, 32 nodes/block
__global__ void gemm2_kernel(const float* __restrict__ b1,
                             const float* __restrict__ W2, int n) {
    __shared__ float4 Ws[64 * 8];    // W2 [64][32] as float4 (8KB)
    __shared__ float  hs[32 * 65];   // hrelu rows, padded
    __shared__ float  b1s[64];
    int tid = threadIdx.y * 8 + threadIdx.x;
    const float4* W4 = (const float4*)W2;
    for (int i = tid; i < 64 * 8; i += 256) Ws[i] = W4[i];
    if (tid < 64) b1s[tid] = b1[tid];
    __syncthreads();
    int base = blockIdx.x * 32;
    const float* agg1f = (const float*)g_agg1;
    for (int i = tid; i < 32 * 64; i += 256) {
        int j = i >> 6, k = i & 63;
        int node = base + j;
        float v = 0.f;
        if (node < n) {
            float dv = g_dinv[node];
            v = fmaxf(dv * agg1f[(size_t)node * 64 + k] + b1s[k], 0.f);
        }
        hs[j * 65 + k] = v;
    }
    __syncthreads();
    int fx = threadIdx.x, j = threadIdx.y;
    float4 acc = make_float4(0.f, 0.f, 0.f, 0.f);
    const float* hr = &hs[j * 65];
#pragma unroll
    for (int k = 0; k < 64; k++) {
        float xv = hr[k];
        float4 w = Ws[k * 8 + fx];
        acc.x += xv * w.x; acc.y += xv * w.y;
        acc.z += xv * w.z; acc.w += xv * w.w;
    }
    int node = base + j;
    if (node < n) {
        float dv = g_dinv[node];
        float4 gv = make_float4(acc.x * dv, acc.y * dv, acc.z * dv, acc.w * dv);
        g_g2[node * 8 + fx]   = gv;
        g_agg2[node * 8 + fx] = gv;
    }
}

// layer2 scatter: agg2[dst] += g2[src]   (8 threads/edge)
__global__ void edge2_kernel(const void* __restrict__ ei, int e) {
    unsigned int t = blockIdx.x * blockDim.x + threadIdx.x;
    if (t >= (unsigned int)e * 8u) return;
    int eid = (int)(t >> 3), c = (int)(t & 7u);
    int is64 = g_idx64;
    int s, d;
    if (is64) {
        const long long* p = (const long long*)ei;
        s = (int)p[eid]; d = (int)p[(size_t)e + eid];
    } else {
        const int* p = (const int*)ei;
        s = p[eid]; d = p[(size_t)e + eid];
    }
    float4 v = g_g2[(size_t)s * 8 + c];
    red_add_v4((float*)g_agg2 + (size_t)d * 32 + c * 4, v);
}

// epilogue2 + heads: h = dinv*agg2 + b2; mu = h@Wmu + bmu; lv = h@Wlv + blv
// block: (8,32) = 256 thr, 32 nodes/block
__global__ void final_kernel(const float* __restrict__ b2,
                             const float* __restrict__ Wmu,
                             const float* __restrict__ bmu,
                             const float* __restrict__ Wlv,
                             const float* __restrict__ blv,
                             float* __restrict__ out, int n) {
    __shared__ float4 Wm[32 * 8];    // 4KB
    __shared__ float4 Wl[32 * 8];    // 4KB
    __shared__ float  hs[32 * 33];
    __shared__ float  b2s[32];
    int tid = threadIdx.y * 8 + threadIdx.x;
    for (int i = tid; i < 32 * 8; i += 256) {
        Wm[i] = ((const float4*)Wmu)[i];
        Wl[i] = ((const float4*)Wlv)[i];
    }
    if (tid < 32) b2s[tid] = b2[tid];
    __syncthreads();
    int base = blockIdx.x * 32;
    const float* agg2f = (const float*)g_agg2;
    for (int i = tid; i < 32 * 32; i += 256) {
        int j = i >> 5, k = i & 31;
        int node = base + j;
        float v = 0.f;
        if (node < n) v = g_dinv[node] * agg2f[(size_t)node * 32 + k] + b2s[k];
        hs[j * 33 + k] = v;
    }
    __syncthreads();
    int fx = threadIdx.x, j = threadIdx.y;
    float4 am = ((const float4*)bmu)[fx];
    float4 al = ((const float4*)blv)[fx];
    const float* hr = &hs[j * 33];
#pragma unroll
    for (int k = 0; k < 32; k++) {
        float xv = hr[k];
        float4 wm = Wm[k * 8 + fx];
        float4 wl = Wl[k * 8 + fx];
        am.x += xv * wm.x; am.y += xv * wm.y; am.z += xv * wm.z; am.w += xv * wm.w;
        al.x += xv * wl.x; al.y += xv * wl.y; al.z += xv * wl.z; al.w += xv * wl.w;
    }
    int node = base + j;
    if (node < n) {
        ((float4*)out)[(size_t)node * 8 + fx] = am;
        ((float4*)(out + (size_t)n * 32))[(size_t)node * 8 + fx] = al;
    }
}

extern "C" void kernel_launch(void* const* d_in, const int* in_sizes, int n_in,
                              void* d_out, int out_size) {
    const float* x   = (const float*)d_in[0];
    const void*  ei  = d_in[1];                 // int64 or int32, detected on device
    const float* W1  = (const float*)d_in[2];
    const float* b1  = (const float*)d_in[3];
    const float* W2  = (const float*)d_in[4];
    const float* b2  = (const float*)d_in[5];
    const float* Wmu = (const float*)d_in[6];
    const float* bmu = (const float*)d_in[7];
    const float* Wlv = (const float*)d_in[8];
    const float* blv = (const float*)d_in[9];
    float* out = (float*)d_out;

    int n = in_sizes[0] / 128;     // 100000
    int e = in_sizes[1] / 2;       // 1600000

    detect_kernel<<<1, 32>>>((const unsigned int*)ei);
    deg_init_kernel<<<(n + 255) / 256, 256>>>(n);
    deg_count_kernel<<<(e + 255) / 256, 256>>>(ei, e);
    dinv_kernel<<<(n + 255) / 256, 256>>>(n);

    dim3 b16(16, 16);
    gemm1_kernel<<<(n + 15) / 16, b16>>>(x, W1, n);

    {
        unsigned int tot = (unsigned int)e * 16u;
        edge1_kernel<<<(tot + 255u) / 256u, 256>>>(ei, e);
    }

    dim3 b832(8, 32);
    gemm2_kernel<<<(n + 31) / 32, b832>>>(b1, W2, n);

    {
        unsigned int tot = (unsigned int)e * 8u;
        edge2_kernel<<<(tot + 255u) / 256u, 256>>>(ei, e);
    }

    final_kernel<<<(n + 31) / 32, b832>>>(b2, Wmu, bmu, Wlv, blv, out, n);
}

// round 5
// speedup vs baseline: 1.8784x; 1.8784x over previous
#include <cuda_runtime.h>
#include <cstdint>

#define NMAX 100000
#define EMAX 2000000

// ---- scratch (__device__ globals; no allocations allowed) ----
__device__ int    g_deg[NMAX];
__device__ float  g_dinv[NMAX];
__device__ int    g_ptr[NMAX + 1];
__device__ int    g_cursor[NMAX];
__device__ int    g_bsums[128];
__device__ int    g_boffs[128];
__device__ int    g_csr[EMAX];
__device__ float4 g_g1[NMAX * 16];   // dinv*(x@W1)   [N,64]
__device__ float  g_h1[NMAX * 64];   // relu(dinv*agg1 + b1)
__device__ float4 g_g2[NMAX * 8];    // dinv*(h1@W2)  [N,32]
__device__ int    g_idx64;

// ---------- int64/int32 edge dtype detection ----------
__global__ void detect_kernel(const unsigned int* __restrict__ w) {
    if (threadIdx.x == 0 && blockIdx.x == 0) {
        int all0 = 1;
        for (int i = 1; i < 129; i += 2) all0 &= (w[i] == 0u);
        g_idx64 = all0;
    }
}

__global__ void deg_init_kernel(int n) {
    int i = blockIdx.x * blockDim.x + threadIdx.x;
    if (i < n) g_deg[i] = 1;  // self-loop
}

__global__ void deg_count_kernel(const void* __restrict__ ei, int e) {
    int i = blockIdx.x * blockDim.x + threadIdx.x;
    if (i >= e) return;
    int d;
    if (g_idx64) d = (int)((const long long*)ei)[(size_t)e + i];
    else         d = ((const int*)ei)[(size_t)e + i];
    atomicAdd(&g_deg[d], 1);
}

// ---------- 3-phase exclusive prefix scan of deg -> ptr ----------
// scan1: 1024 elems/block (256 thr x 4), local exclusive scan + block sum
__global__ void scan1_kernel(int n) {
    __shared__ int tsum[256];
    int t = threadIdx.x;
    int base = blockIdx.x * 1024 + t * 4;
    int v[4], s = 0;
#pragma unroll
    for (int q = 0; q < 4; q++) {
        int i = base + q;
        v[q] = (i < n) ? g_deg[i] : 0;
        s += v[q];
    }
    tsum[t] = s;
    __syncthreads();
    for (int off = 1; off < 256; off <<= 1) {
        int x = (t >= off) ? tsum[t - off] : 0;
        __syncthreads();
        tsum[t] += x;
        __syncthreads();
    }
    int excl = tsum[t] - s;
#pragma unroll
    for (int q = 0; q < 4; q++) {
        int i = base + q;
        if (i < n) g_ptr[i] = excl;
        excl += v[q];
    }
    if (t == 255) g_bsums[blockIdx.x] = tsum[255];
}

// scan2: single block scans block sums (<=128)
__global__ void scan2_kernel(int nblocks, int n) {
    __shared__ int sh[128];
    int t = threadIdx.x;
    int v = (t < nblocks) ? g_bsums[t] : 0;
    sh[t] = v;
    __syncthreads();
    for (int off = 1; off < 128; off <<= 1) {
        int x = (t >= off) ? sh[t - off] : 0;
        __syncthreads();
        sh[t] += x;
        __syncthreads();
    }
    g_boffs[t] = sh[t] - v;
    if (t == 127) g_ptr[n] = sh[127];  // total = E + N
}

// scan3: add block offsets, init cursor, compute dinv
__global__ void scan3_kernel(int n) {
    int i = blockIdx.x * blockDim.x + threadIdx.x;
    if (i >= n) return;
    int p = g_ptr[i] + g_boffs[i >> 10];
    g_ptr[i] = p;
    g_cursor[i] = p;
    g_dinv[i] = rsqrtf((float)g_deg[i]);
}

// fill CSR: srcs grouped by dst (self-loops excluded; seeded in pull via init)
__global__ void scatter_fill_kernel(const void* __restrict__ ei, int e) {
    int i = blockIdx.x * blockDim.x + threadIdx.x;
    if (i >= e) return;
    int s, d;
    if (g_idx64) {
        const long long* p = (const long long*)ei;
        s = (int)p[i]; d = (int)p[(size_t)e + i];
    } else {
        const int* p = (const int*)ei;
        s = p[i]; d = p[(size_t)e + i];
    }
    int pos = atomicAdd(&g_cursor[d], 1) + 1;  // +1: slot 0 reserved... (see note)
    // NOTE: cursor starts at ptr[d]; edges occupy [ptr[d]+1 .. ptr[d]+deg-1]?
    // No — self-loop is NOT stored in CSR; it's the register init in pull.
    // So edges must occupy [ptr[d] .. ptr[d]+indeg-1]. Undo the +1:
    g_csr[pos - 1] = s;
}

// ---------- GEMM1: g1 = dinv * (x @ W1), reg-tiled 128x64, thread 8x8 ----------
__global__ __launch_bounds__(128) void gemm1_kernel(
        const float* __restrict__ x, const float* __restrict__ W1, int n) {
    __shared__ __align__(16) float xs[32 * 136];  // [k][node] transposed, padded
    __shared__ __align__(16) float ws[32 * 64];   // [k][feat]
    int fx = threadIdx.x;           // 0..7  -> feats fx*8..fx*8+7
    int ty = threadIdx.y;           // 0..15 -> nodes ty*8..ty*8+7
    int tid = ty * 8 + fx;
    int nbase = blockIdx.x * 128;
    float acc[8][8];
#pragma unroll
    for (int i = 0; i < 8; i++)
#pragma unroll
        for (int j = 0; j < 8; j++) acc[i][j] = 0.f;

    const float4* x4 = (const float4*)x;
    for (int k0 = 0; k0 < 128; k0 += 32) {
        __syncthreads();
        {   // stage x chunk: node = tid
            int node = nbase + tid;
            int nodec = node < n ? node : (n - 1);
            const float4* row = x4 + (size_t)nodec * 32 + (k0 >> 2);
#pragma unroll
            for (int q = 0; q < 8; q++) {
                float4 v = row[q];
                int kk = q * 4;
                xs[(kk + 0) * 136 + tid] = v.x;
                xs[(kk + 1) * 136 + tid] = v.y;
                xs[(kk + 2) * 136 + tid] = v.z;
                xs[(kk + 3) * 136 + tid] = v.w;
            }
        }
        {   // stage W chunk rows k0..k0+31 (512 float4)
            const float4* wsrc = (const float4*)W1 + k0 * 16;
            float4* wd = (float4*)ws;
#pragma unroll
            for (int q = 0; q < 4; q++) wd[q * 128 + tid] = wsrc[q * 128 + tid];
        }
        __syncthreads();
#pragma unroll 4
        for (int kk = 0; kk < 32; kk++) {
            float4 xa = *(const float4*)&xs[kk * 136 + ty * 8];
            float4 xb = *(const float4*)&xs[kk * 136 + ty * 8 + 4];
            float4 wa = *(const float4*)&ws[kk * 64 + fx * 8];
            float4 wb = *(const float4*)&ws[kk * 64 + fx * 8 + 4];
            float xv[8] = {xa.x, xa.y, xa.z, xa.w, xb.x, xb.y, xb.z, xb.w};
            float wv[8] = {wa.x, wa.y, wa.z, wa.w, wb.x, wb.y, wb.z, wb.w};
#pragma unroll
            for (int i = 0; i < 8; i++)
#pragma unroll
                for (int j = 0; j < 8; j++) acc[i][j] += xv[i] * wv[j];
        }
    }
#pragma unroll
    for (int i = 0; i < 8; i++) {
        int node = nbase + ty * 8 + i;
        if (node < n) {
            float dv = g_dinv[node];
            float4 a = make_float4(acc[i][0] * dv, acc[i][1] * dv,
                                   acc[i][2] * dv, acc[i][3] * dv);
            float4 b = make_float4(acc[i][4] * dv, acc[i][5] * dv,
                                   acc[i][6] * dv, acc[i][7] * dv);
            g_g1[(size_t)node * 16 + fx * 2]     = a;
            g_g1[(size_t)node * 16 + fx * 2 + 1] = b;
        }
    }
}

// ---------- pull1: h1 = relu(dinv * (self + sum_in g1[src]) + b1) ----------
__global__ void pull1_kernel(const float* __restrict__ b1, int n) {
    int t = blockIdx.x * blockDim.x + threadIdx.x;
    int node = t >> 4, c = t & 15;
    if (node >= n) return;
    int beg = g_ptr[node], end = g_ptr[node + 1] - 1;  // indeg excl self = deg-1
    float4 acc = g_g1[(size_t)node * 16 + c];          // self-loop seed
    int i = beg;
    for (; i + 2 <= end; i += 2) {
        int s0 = g_csr[i], s1 = g_csr[i + 1];
        float4 v0 = g_g1[(size_t)s0 * 16 + c];
        float4 v1 = g_g1[(size_t)s1 * 16 + c];
        acc.x += v0.x + v1.x; acc.y += v0.y + v1.y;
        acc.z += v0.z + v1.z; acc.w += v0.w + v1.w;
    }
    if (i < end) {
        int s = g_csr[i];
        float4 v = g_g1[(size_t)s * 16 + c];
        acc.x += v.x; acc.y += v.y; acc.z += v.z; acc.w += v.w;
    }
    float dv = g_dinv[node];
    float4 bb = ((const float4*)b1)[c];
    float4 h;
    h.x = fmaxf(fmaf(dv, acc.x, bb.x), 0.f);
    h.y = fmaxf(fmaf(dv, acc.y, bb.y), 0.f);
    h.z = fmaxf(fmaf(dv, acc.z, bb.z), 0.f);
    h.w = fmaxf(fmaf(dv, acc.w, bb.w), 0.f);
    *(float4*)&g_h1[(size_t)node * 64 + c * 4] = h;
}

// ---------- GEMM2: g2 = dinv * (h1 @ W2), tile 128x32, thread 8x4 ----------
__global__ __launch_bounds__(128) void gemm2_kernel(
        const float* __restrict__ W2, int n) {
    __shared__ __align__(16) float hs[64 * 136];  // [k][node]
    __shared__ __align__(16) float ws[64 * 32];   // [k][feat]
    int fx = threadIdx.x;   // 0..7 -> feats fx*4..fx*4+3
    int ty = threadIdx.y;   // 0..15 -> nodes ty*8..
    int tid = ty * 8 + fx;
    int nbase = blockIdx.x * 128;
    float acc[8][4];
#pragma unroll
    for (int i = 0; i < 8; i++)
#pragma unroll
        for (int j = 0; j < 4; j++) acc[i][j] = 0.f;

    {   // stage h1 (full K=64): node = tid, 16 float4 per node
        int node = nbase + tid;
        int nodec = node < n ? node : (n - 1);
        const float4* row = (const float4*)&g_h1[(size_t)nodec * 64];
#pragma unroll
        for (int q = 0; q < 16; q++) {
            float4 v = row[q];
            int kk = q * 4;
            hs[(kk + 0) * 136 + tid] = v.x;
            hs[(kk + 1) * 136 + tid] = v.y;
            hs[(kk + 2) * 136 + tid] = v.z;
            hs[(kk + 3) * 136 + tid] = v.w;
        }
    }
    {   // stage W2 (64x32 = 512 float4)
        const float4* wsrc = (const float4*)W2;
        float4* wd = (float4*)ws;
#pragma unroll
        for (int q = 0; q < 4; q++) wd[q * 128 + tid] = wsrc[q * 128 + tid];
    }
    __syncthreads();
#pragma unroll 4
    for (int kk = 0; kk < 64; kk++) {
        float4 xa = *(const float4*)&hs[kk * 136 + ty * 8];
        float4 xb = *(const float4*)&hs[kk * 136 + ty * 8 + 4];
        float4 w  = *(const float4*)&ws[kk * 32 + fx * 4];
        float xv[8] = {xa.x, xa.y, xa.z, xa.w, xb.x, xb.y, xb.z, xb.w};
        float wv[4] = {w.x, w.y, w.z, w.w};
#pragma unroll
        for (int i = 0; i < 8; i++)
#pragma unroll
            for (int j = 0; j < 4; j++) acc[i][j] += xv[i] * wv[j];
    }
#pragma unroll
    for (int i = 0; i < 8; i++) {
        int node = nbase + ty * 8 + i;
        if (node < n) {
            float dv = g_dinv[node];
            g_g2[(size_t)node * 8 + fx] =
                make_float4(acc[i][0] * dv, acc[i][1] * dv,
                            acc[i][2] * dv, acc[i][3] * dv);
        }
    }
}

// ---------- pull2 + heads: h = dinv*agg2 + b2; out = [h@Wmu+bmu ; h@Wlv+blv] ----------
__global__ void pull2_kernel(const float* __restrict__ b2,
                             const float* __restrict__ Wmu,
                             const float* __restrict__ bmu,
                             const float* __restrict__ Wlv,
                             const float* __restrict__ blv,
                             float* __restrict__ out, int n) {
    __shared__ float  hsm[32 * 33];
    __shared__ float4 wm[32 * 8];
    __shared__ float4 wl[32 * 8];
    int tid = threadIdx.x;           // 256
    int j = tid >> 3, fx = tid & 7;  // 32 nodes x 8 feat-quads
    wm[tid] = ((const float4*)Wmu)[tid];
    wl[tid] = ((const float4*)Wlv)[tid];
    int node = blockIdx.x * 32 + j;
    int nodec = node < n ? node : (n - 1);

    int beg = g_ptr[nodec], end = g_ptr[nodec + 1] - 1;
    float4 acc = g_g2[(size_t)nodec * 8 + fx];  // self-loop seed
    int i = beg;
    for (; i + 2 <= end; i += 2) {
        int s0 = g_csr[i], s1 = g_csr[i + 1];
        float4 v0 = g_g2[(size_t)s0 * 8 + fx];
        float4 v1 = g_g2[(size_t)s1 * 8 + fx];
        acc.x += v0.x + v1.x; acc.y += v0.y + v1.y;
        acc.z += v0.z + v1.z; acc.w += v0.w + v1.w;
    }
    if (i < end) {
        int s = g_csr[i];
        float4 v = g_g2[(size_t)s * 8 + fx];
        acc.x += v.x; acc.y += v.y; acc.z += v.z; acc.w += v.w;
    }
    float dv = g_dinv[nodec];
    float4 bb = ((const float4*)b2)[fx];
    hsm[j * 33 + fx * 4 + 0] = fmaf(dv, acc.x, bb.x);
    hsm[j * 33 + fx * 4 + 1] = fmaf(dv, acc.y, bb.y);
    hsm[j * 33 + fx * 4 + 2] = fmaf(dv, acc.z, bb.z);
    hsm[j * 33 + fx * 4 + 3] = fmaf(dv, acc.w, bb.w);
    __syncthreads();

    float4 am = ((const float4*)bmu)[fx];
    float4 al = ((const float4*)blv)[fx];
    const float* hr = &hsm[j * 33];
#pragma unroll
    for (int k = 0; k < 32; k++) {
        float hv = hr[k];
        float4 m = wm[k * 8 + fx];
        float4 l = wl[k * 8 + fx];
        am.x += hv * m.x; am.y += hv * m.y; am.z += hv * m.z; am.w += hv * m.w;
        al.x += hv * l.x; al.y += hv * l.y; al.z += hv * l.z; al.w += hv * l.w;
    }
    if (node < n) {
        ((float4*)out)[(size_t)node * 8 + fx] = am;
        ((float4*)(out + (size_t)n * 32))[(size_t)node * 8 + fx] = al;
    }
}

extern "C" void kernel_launch(void* const* d_in, const int* in_sizes, int n_in,
                              void* d_out, int out_size) {
    const float* x   = (const float*)d_in[0];
    const void*  ei  = d_in[1];
    const float* W1  = (const float*)d_in[2];
    const float* b1  = (const float*)d_in[3];
    const float* W2  = (const float*)d_in[4];
    const float* b2  = (const float*)d_in[5];
    const float* Wmu = (const float*)d_in[6];
    const float* bmu = (const float*)d_in[7];
    const float* Wlv = (const float*)d_in[8];
    const float* blv = (const float*)d_in[9];
    float* out = (float*)d_out;

    int n = in_sizes[0] / 128;   // 100000
    int e = in_sizes[1] / 2;     // 1600000

    detect_kernel<<<1, 32>>>((const unsigned int*)ei);
    deg_init_kernel<<<(n + 255) / 256, 256>>>(n);
    deg_count_kernel<<<(e + 255) / 256, 256>>>(ei, e);

    int nscan = (n + 1023) / 1024;        // <=128
    scan1_kernel<<<nscan, 256>>>(n);
    scan2_kernel<<<1, 128>>>(nscan, n);
    scan3_kernel<<<(n + 255) / 256, 256>>>(n);
    scatter_fill_kernel<<<(e + 255) / 256, 256>>>(ei, e);

    dim3 gth(8, 16);
    gemm1_kernel<<<(n + 127) / 128, gth>>>(x, W1, n);
    pull1_kernel<<<(n * 16 + 255) / 256, 256>>>(b1, n);
    gemm2_kernel<<<(n + 127) / 128, gth>>>(W2, n);
    pull2_kernel<<<(n + 31) / 32, 256>>>(b2, Wmu, bmu, Wlv, blv, out, n);
}